// round 3
// baseline (speedup 1.0000x reference)
#include <cuda_runtime.h>
#include <cuda_bf16.h>
#include <cstdint>

// Problem constants (from reference): N_VOXELS=80000, C=64, NX=NY=512, B=4
#define NXC   512
#define NYC   512
#define CCH   64
#define BATCHN 4
#define PLANE (NXC * NYC)            // 262144 spatial slots per batch
#define SLOTS (BATCHN * PLANE)       // 1048576 total slots

// Scratch: per-slot winning voxel index (-1 = empty). 4 MB __device__ global
// (no allocation allowed in kernel_launch).
__device__ int g_winner[SLOTS];

// ---------------------------------------------------------------------------
// Kernel 1: reset winner array to -1 (vectorized int4 stores, 4 MB write)
// ---------------------------------------------------------------------------
__global__ void fill_winner_kernel() {
    int i = blockIdx.x * blockDim.x + threadIdx.x;   // quad index
    if (i < SLOTS / 4) {
        ((int4*)g_winner)[i] = make_int4(-1, -1, -1, -1);
    }
}

// ---------------------------------------------------------------------------
// Kernel 2: each voxel votes for its slot; highest voxel index wins
// (emulates serial scatter "last write wins" semantics deterministically)
// ---------------------------------------------------------------------------
__global__ void vote_kernel(const int* __restrict__ coords, int n) {
    int i = blockIdx.x * blockDim.x + threadIdx.x;
    if (i < n) {
        int b = coords[3 * i + 0];
        int x = coords[3 * i + 1];
        int y = coords[3 * i + 2];
        int slot = b * PLANE + x * NYC + y;
        atomicMax(&g_winner[slot], i);
    }
}

// ---------------------------------------------------------------------------
// Kernel 3: gather-write the full output canvas.
// out layout: [B, C, NX, NY] row-major -> o = ((b*C + c)*NX + x)*NY + y
// Each thread writes one float4 (4 consecutive y positions, same b,c).
// winner reads are consecutive -> LDG.128 from L2 (4 MB array, fully cached).
// feat reads are random 4B but the 20 MB feature array lives in L2.
// Output write is a perfectly coalesced 256 MB stream -> the DRAM floor.
// ---------------------------------------------------------------------------
__global__ void gather_kernel(const float* __restrict__ feat,
                              float* __restrict__ out) {
    int q = blockIdx.x * blockDim.x + threadIdx.x;   // quad index
    // total quads = BATCHN * CCH * PLANE / 4 = 16,777,216 (fits in int)
    int idx = q << 2;                                 // element index
    int b   = idx / (CCH * PLANE);
    int rem = idx - b * (CCH * PLANE);
    int c   = rem / PLANE;
    int p   = rem - c * PLANE;                        // p..p+3 same (b,c), PLANE%4==0

    const int4 w4 = *((const int4*)&g_winner[b * PLANE + p]);

    float4 v;
    v.x = (w4.x >= 0) ? __ldg(&feat[w4.x * CCH + c]) : 0.0f;
    v.y = (w4.y >= 0) ? __ldg(&feat[w4.y * CCH + c]) : 0.0f;
    v.z = (w4.z >= 0) ? __ldg(&feat[w4.z * CCH + c]) : 0.0f;
    v.w = (w4.w >= 0) ? __ldg(&feat[w4.w * CCH + c]) : 0.0f;

    ((float4*)out)[q] = v;
}

// ---------------------------------------------------------------------------
extern "C" void kernel_launch(void* const* d_in, const int* in_sizes, int n_in,
                              void* d_out, int out_size) {
    const float* feat   = (const float*)d_in[0];   // [N, 64] fp32
    const int*   coords = (const int*)d_in[1];     // [N, 3]  int32
    const int n = in_sizes[0] / CCH;               // number of voxels

    // 1) reset winner array
    {
        int quads = SLOTS / 4;                      // 262144
        fill_winner_kernel<<<(quads + 255) / 256, 256>>>();
    }
    // 2) vote (last voxel index wins per slot)
    vote_kernel<<<(n + 255) / 256, 256>>>(coords, n);
    // 3) fused zero-fill + scatter as a coalesced gather over the output
    {
        int quads = out_size / 4;                   // 16,777,216
        gather_kernel<<<(quads + 255) / 256, 256>>>(feat, (float*)d_out);
    }
}